// round 12
// baseline (speedup 1.0000x reference)
#include <cuda_runtime.h>
#include <cuda_fp16.h>
#include <mma.h>
#include <cstdint>

using namespace nvcuda;

#define N_NODES_MAX 50000
#define N_EDGES_MAX 800000
#define D_FEAT 64
#define D_OUT 64
#define N_REL 8
#define KTOT 512          /* k = i*8 + r (matches x row layout) */
#define KCH 64            /* K per chunk */
#define NCHUNKS (KTOT / KCH)
#define MTILE 128
#define TBLOCK 256
#define LDP 72            /* padded row stride in halves (144B) */
#define SCAN_PER 4096
#define TGRID 296         /* transform grid: 2 blocks/SM x 148 */

typedef unsigned long long ull;

// device scratch (static allocation per harness rules)
__device__ __half   g_y[(size_t)N_NODES_MAX * D_OUT];   // 6.4 MB
__device__ __half   g_wt[KTOT * LDP];                   // fused weights, padded
__device__ int      g_cnt[N_NODES_MAX + 64];            // counts/cursors + scan pub tail
__device__ int      g_start[N_NODES_MAX + 1];
__device__ uint32_t g_elist[N_EDGES_MAX];               // src:16 | half(w):16
__device__ int      g_tilectr;                          // dynamic tile counter

// ---------------------------------------------------------------------------
// Wt build + tile-counter init
// ---------------------------------------------------------------------------
extern "C" __global__ void rgcn_wt_build(const float* __restrict__ w_bases,
                                         const float* __restrict__ w_rel,
                                         int tgrid)
{
    int gid = blockIdx.x * blockDim.x + threadIdx.x;
    if (gid == 0) g_tilectr = tgrid;     // same stream as transform: ordered
    if (gid >= KTOT * D_OUT) return;
    int k = gid >> 6;
    int o = gid & 63;
    int i = k >> 3, r = k & 7;
    float acc = 0.f;
    #pragma unroll
    for (int b = 0; b < 4; b++)
        acc += w_rel[r * 4 + b] * w_bases[(b * D_FEAT + i) * D_OUT + o];
    g_wt[k * LDP + o] = __float2half_rn(acc);
}

// ---------------------------------------------------------------------------
// Transform via wmma (HMMA), dynamic tiles, pipelined conv, 32x32 warp tiles:
//   y[node,o] = sum_k x[node,k] * Wt[k,o]
// ---------------------------------------------------------------------------
extern "C" __global__ void __launch_bounds__(TBLOCK, 2)
rgcn_transform_mma(const float* __restrict__ x, int n_nodes, int n_tiles)
{
    extern __shared__ __align__(16) char smem[];
    __half* wt_s = (__half*)smem;                       // 512*72 halves
    __half* xb   = (__half*)(smem + KTOT * LDP * 2);    // 2*128*72 halves

    const int t = threadIdx.x;
    const int warp = t >> 5;
    const int wm = (warp & 3) * 32;   // warp's 32-row band
    const int wn = (warp >> 2) * 32;  // warp's 32-col band

    {
        const float4* src = (const float4*)g_wt;
        float4* dst = (float4*)wt_s;
        #pragma unroll
        for (int i2 = 0; i2 < 18; i2++) dst[t + i2 * TBLOCK] = src[t + i2 * TBLOCK];
    }
    // wt_s visible by the first in-loop __syncthreads() before any mma.

    int tile = blockIdx.x;
    while (tile < n_tiles) {
        const int node0 = tile * MTILE;

        wmma::fragment<wmma::accumulator, 16, 16, 16, float> facc[2][2];
        #pragma unroll
        for (int mi = 0; mi < 2; mi++)
            #pragma unroll
            for (int ni = 0; ni < 2; ni++) wmma::fill_fragment(facc[mi][ni], 0.0f);

        // prefetch chunk 0 into registers
        float4 pf[8];
        #pragma unroll
        for (int it = 0; it < 8; it++) {
            int f = t + it * TBLOCK;
            int row = f >> 4, c4 = f & 15;
            int node = node0 + row;
            pf[it] = (node < n_nodes)
                ? ((const float4*)x)[(size_t)node * (KTOT / 4) + c4]
                : make_float4(0.f, 0.f, 0.f, 0.f);
        }

        for (int c = 0; c < NCHUNKS; c++) {
            __half* xcur = xb + (c & 1) * (MTILE * LDP);

            // cvt + store prefetched chunk c
            #pragma unroll
            for (int it = 0; it < 8; it++) {
                int f = t + it * TBLOCK;
                int row = f >> 4, c4 = f & 15;
                __half2 h0 = __floats2half2_rn(pf[it].x, pf[it].y);
                __half2 h1 = __floats2half2_rn(pf[it].z, pf[it].w);
                uint2 st;
                st.x = *(uint32_t*)&h0;
                st.y = *(uint32_t*)&h1;
                *(uint2*)((char*)xcur + row * (LDP * 2) + c4 * 8) = st;
            }
            __syncthreads();   // conv(c) visible; mma(c-1) readers of other buf done

            // prefetch chunk c+1 (overlaps with mma below)
            if (c + 1 < NCHUNKS) {
                #pragma unroll
                for (int it = 0; it < 8; it++) {
                    int f = t + it * TBLOCK;
                    int row = f >> 4, c4 = f & 15;
                    int node = node0 + row;
                    pf[it] = (node < n_nodes)
                        ? ((const float4*)x)[(size_t)node * (KTOT / 4) + (c + 1) * 16 + c4]
                        : make_float4(0.f, 0.f, 0.f, 0.f);
                }
            }

            #pragma unroll
            for (int kk = 0; kk < 4; kk++) {
                wmma::fragment<wmma::matrix_a, 16, 16, 16, __half, wmma::row_major> fa[2];
                #pragma unroll
                for (int mi = 0; mi < 2; mi++)
                    wmma::load_matrix_sync(fa[mi],
                        xcur + (wm + mi * 16) * LDP + kk * 16, LDP);
                const __half* wrow = wt_s + (c * KCH + kk * 16) * LDP + wn;
                #pragma unroll
                for (int ni = 0; ni < 2; ni++) {
                    wmma::fragment<wmma::matrix_b, 16, 16, 16, __half, wmma::row_major> fb;
                    wmma::load_matrix_sync(fb, wrow + ni * 16, LDP);
                    #pragma unroll
                    for (int mi = 0; mi < 2; mi++)
                        wmma::mma_sync(facc[mi][ni], fa[mi], fb, facc[mi][ni]);
                }
            }
        }

        __syncthreads();     // all mma reads of xb done (stage spans both bufs)
        float* stage = (float*)xb;
        #pragma unroll
        for (int mi = 0; mi < 2; mi++)
            #pragma unroll
            for (int ni = 0; ni < 2; ni++)
                wmma::store_matrix_sync(stage + (wm + mi * 16) * D_OUT + wn + ni * 16,
                                        facc[mi][ni], D_OUT, wmma::mem_row_major);
        __syncthreads();

        #pragma unroll
        for (int it = 0; it < 8; it++) {
            int f = t + it * TBLOCK;
            int row = f >> 4, q = f & 15;
            int node = node0 + row;
            if (node < n_nodes) {
                float4 v = *(const float4*)(stage + row * D_OUT + q * 4);
                __half2 h0 = __floats2half2_rn(v.x, v.y);
                __half2 h1 = __floats2half2_rn(v.z, v.w);
                uint2 st;
                st.x = *(uint32_t*)&h0;
                st.y = *(uint32_t*)&h1;
                *(uint2*)(g_y + (size_t)node * D_OUT + q * 4) = st;
            }
        }
        __syncthreads();     // stage reads done before next tile's conv writes

        if (t == 0) ((int*)xb)[0] = atomicAdd(&g_tilectr, 1);
        __syncthreads();
        tile = ((int*)xb)[0];
        __syncthreads();
    }
}

// ---------------------------------------------------------------------------
// CSR build: one memset(g_cnt incl. pub tail) -> hist -> fused scan -> fill
// ---------------------------------------------------------------------------
extern "C" __global__ void rgcn_hist(const int* __restrict__ edst, int n_edges)
{
    int e = blockIdx.x * blockDim.x + threadIdx.x;
    if (e < n_edges) atomicAdd(&g_cnt[edst[e]], 1);
}

// single-pass scan, grid <= 16 blocks, parallel publish/poll
extern "C" __global__ void __launch_bounds__(1024, 1)
rgcn_scan_fused(int n_nodes)
{
    __shared__ int wtot[32];
    __shared__ int preds[16];
    __shared__ int bp_sh;
    const int t = threadIdx.x, lane = t & 31, wid = t >> 5;
    const int b = blockIdx.x;
    volatile ull* pub = (volatile ull*)(g_cnt + ((n_nodes + 1) & ~1));

    int base = b * SCAN_PER + t * 4;
    int v[4];
    if (base + 3 < n_nodes) {
        int4 q = *(const int4*)(g_cnt + base);
        v[0] = q.x; v[1] = q.y; v[2] = q.z; v[3] = q.w;
    } else {
        #pragma unroll
        for (int j = 0; j < 4; j++) {
            int idx = base + j;
            v[j] = (idx < n_nodes) ? g_cnt[idx] : 0;
        }
    }
    int tsum = v[0] + v[1] + v[2] + v[3];
    int s = tsum;
    #pragma unroll
    for (int d = 1; d < 32; d <<= 1) {
        int u = __shfl_up_sync(0xffffffffu, s, d);
        if (lane >= d) s += u;
    }
    if (lane == 31) wtot[wid] = s;
    __syncthreads();
    if (wid == 0) {
        int wv = wtot[lane];
        #pragma unroll
        for (int d = 1; d < 32; d <<= 1) {
            int u = __shfl_up_sync(0xffffffffu, wv, d);
            if (lane >= d) wv += u;
        }
        wtot[lane] = wv;
    }
    __syncthreads();
    int local_excl = (s - tsum) + (wid ? wtot[wid - 1] : 0);
    int block_total = wtot[31];

    if (t == 0)
        pub[b] = (1ULL << 32) | (unsigned)block_total;
    if (t < b) {
        ull pv;
        do { pv = pub[t]; } while ((pv >> 32) == 0);
        preds[t] = (int)(unsigned)pv;
    }
    __syncthreads();
    if (t == 0) {
        int r = 0;
        for (int j = 0; j < b; j++) r += preds[j];
        bp_sh = r;
    }
    __syncthreads();

    int off = bp_sh + local_excl;
    #pragma unroll
    for (int j = 0; j < 4; j++) {
        int idx = base + j;
        if (idx < n_nodes) {
            g_start[idx] = off;
            g_cnt[idx]   = off;
            if (idx == n_nodes - 1) g_start[n_nodes] = off + v[j];
            off += v[j];
        }
    }
}

extern "C" __global__ void rgcn_fill(const int*   __restrict__ esrc,
                                     const int*   __restrict__ edst,
                                     const float* __restrict__ ew,
                                     int n_edges)
{
    int e = blockIdx.x * blockDim.x + threadIdx.x;
    if (e >= n_edges) return;
    int d = edst[e];
    int pos = atomicAdd(&g_cnt[d], 1);
    __half hw = __float2half_rn(ew[e]);
    g_elist[pos] = (uint32_t)esrc[e] | ((uint32_t)*(unsigned short*)&hw << 16);
}

// ---------------------------------------------------------------------------
// Aggregate: one warp per dst node; each lane owns 2 outputs. No atomics.
// ---------------------------------------------------------------------------
__device__ __forceinline__ float2 yfrag(uint32_t src, int lane)
{
    unsigned q = *((const unsigned*)g_y + ((size_t)src << 5) + lane);
    __half2 h; *(unsigned*)&h = q;
    return __half22float2(h);
}

extern "C" __global__ void __launch_bounds__(256, 6)
rgcn_aggregate(float* __restrict__ out, int n_nodes)
{
    int gid = blockIdx.x * blockDim.x + threadIdx.x;
    int n = gid >> 5;
    if (n >= n_nodes) return;
    int lane = gid & 31;
    int e  = g_start[n];
    int e1 = g_start[n + 1];
    float2 acc = make_float2(0.f, 0.f);

    for (; e + 8 <= e1; e += 8) {
        uint32_t p[8];
        #pragma unroll
        for (int j = 0; j < 8; j++) p[j] = g_elist[e + j];
        float2 f[8];
        #pragma unroll
        for (int j = 0; j < 8; j++) f[j] = yfrag(p[j] & 0xFFFFu, lane);
        #pragma unroll
        for (int j = 0; j < 8; j++) {
            unsigned short wb = (unsigned short)(p[j] >> 16);
            float w = __half2float(*(__half*)&wb);
            acc.x += w * f[j].x;
            acc.y += w * f[j].y;
        }
    }
    if (e + 4 <= e1) {
        uint32_t p[4];
        #pragma unroll
        for (int j = 0; j < 4; j++) p[j] = g_elist[e + j];
        float2 f[4];
        #pragma unroll
        for (int j = 0; j < 4; j++) f[j] = yfrag(p[j] & 0xFFFFu, lane);
        #pragma unroll
        for (int j = 0; j < 4; j++) {
            unsigned short wb = (unsigned short)(p[j] >> 16);
            float w = __half2float(*(__half*)&wb);
            acc.x += w * f[j].x;
            acc.y += w * f[j].y;
        }
        e += 4;
    }
    for (; e < e1; e++) {
        uint32_t p = g_elist[e];
        float2 f = yfrag(p & 0xFFFFu, lane);
        unsigned short wb = (unsigned short)(p >> 16);
        float w = __half2float(*(__half*)&wb);
        acc.x += w * f.x;
        acc.y += w * f.y;
    }
    *(float2*)(out + (size_t)n * D_OUT + lane * 2) = acc;
}

// ---------------------------------------------------------------------------
extern "C" void kernel_launch(void* const* d_in, const int* in_sizes, int n_in,
                              void* d_out, int out_size)
{
    const float* x    = (const float*)d_in[0];
    const int*   esrc = (const int*)  d_in[1];
    const int*   edst = (const int*)  d_in[2];
    const float* ew   = (const float*)d_in[3];
    const float* wb   = (const float*)d_in[4];
    const float* wrel = (const float*)d_in[5];
    float* out = (float*)d_out;

    const int n_nodes = in_sizes[0] / (D_FEAT * N_REL);
    const int n_edges = in_sizes[1];
    const int n_tiles = (n_nodes + MTILE - 1) / MTILE;
    const int scan_blocks = (n_nodes + SCAN_PER - 1) / SCAN_PER;
    const int tgrid = n_tiles < TGRID ? n_tiles : TGRID;

    const int mma_smem = KTOT * LDP * 2 + 2 * MTILE * LDP * 2;   // 110592
    cudaFuncSetAttribute(rgcn_transform_mma,
                         cudaFuncAttributeMaxDynamicSharedMemorySize, mma_smem);

    // fork stream + events (host-side; outside graph replay cost)
    cudaStream_t s1;
    cudaStreamCreateWithFlags(&s1, cudaStreamNonBlocking);
    cudaEvent_t evFork, evJoin;
    cudaEventCreateWithFlags(&evFork, cudaEventDisableTiming);
    cudaEventCreateWithFlags(&evJoin, cudaEventDisableTiming);

    // branch A (s1): weights + counter init + HMMA transform (dynamic tiles)
    cudaEventRecord(evFork, 0);
    cudaStreamWaitEvent(s1, evFork, 0);
    rgcn_wt_build<<<(KTOT * D_OUT + 255) / 256, 256, 0, s1>>>(wb, wrel, tgrid);
    rgcn_transform_mma<<<tgrid, TBLOCK, mma_smem, s1>>>(x, n_nodes, n_tiles);
    cudaEventRecord(evJoin, s1);

    // branch B (main): CSR build by dst. One memset covers counters + pub tail.
    void* cnt_ptr = nullptr;
    cudaGetSymbolAddress(&cnt_ptr, g_cnt);
    size_t zero_bytes = (size_t)(((n_nodes + 1) & ~1) + 32) * sizeof(int);
    cudaMemsetAsync(cnt_ptr, 0, zero_bytes, 0);

    rgcn_hist<<<(n_edges + 255) / 256, 256>>>(edst, n_edges);
    rgcn_scan_fused<<<scan_blocks, 1024>>>(n_nodes);
    rgcn_fill<<<(n_edges + 255) / 256, 256>>>(esrc, edst, ew, n_edges);

    // join, then gather-aggregate
    cudaStreamWaitEvent(0, evJoin, 0);
    int total_thr = n_nodes * 32;
    rgcn_aggregate<<<(total_thr + 255) / 256, 256>>>(out, n_nodes);
}

// round 13
// speedup vs baseline: 1.1552x; 1.1552x over previous
#include <cuda_runtime.h>
#include <cuda_fp16.h>
#include <mma.h>
#include <cstdint>

using namespace nvcuda;

#define N_NODES_MAX 50000
#define N_EDGES_MAX 800000
#define D_FEAT 64
#define D_OUT 64
#define N_REL 8
#define KTOT 512          /* k = i*8 + r (matches x row layout) */
#define KCH 64            /* K per chunk */
#define NCHUNKS (KTOT / KCH)
#define MTILE 64
#define TBLOCK 256
#define LDP 72            /* padded row stride in halves (144B) */
#define SCAN_PER 4096
#define TGRID 296         /* transform grid: 2 blocks/SM x 148 */

typedef unsigned long long ull;

// device scratch (static allocation per harness rules)
__device__ __half   g_y[(size_t)N_NODES_MAX * D_OUT];   // 6.4 MB
__device__ __half   g_wt[KTOT * LDP];                   // fused weights, padded
__device__ int      g_cnt[N_NODES_MAX + 64];            // counts/cursors + scan pub tail
__device__ int      g_start[N_NODES_MAX + 1];
__device__ uint32_t g_elist[N_EDGES_MAX];               // src:16 | half(w):16
__device__ int      g_tilectr;                          // dynamic tile counter

// ---------------------------------------------------------------------------
// Wt build + tile-counter init
// ---------------------------------------------------------------------------
extern "C" __global__ void rgcn_wt_build(const float* __restrict__ w_bases,
                                         const float* __restrict__ w_rel,
                                         int tgrid)
{
    int gid = blockIdx.x * blockDim.x + threadIdx.x;
    if (gid == 0) g_tilectr = tgrid;     // same stream as transform: ordered
    if (gid >= KTOT * D_OUT) return;
    int k = gid >> 6;
    int o = gid & 63;
    int i = k >> 3, r = k & 7;
    float acc = 0.f;
    #pragma unroll
    for (int b = 0; b < 4; b++)
        acc += w_rel[r * 4 + b] * w_bases[(b * D_FEAT + i) * D_OUT + o];
    g_wt[k * LDP + o] = __float2half_rn(acc);
}

// ---------------------------------------------------------------------------
// Transform via wmma (HMMA), dynamic 64-row tiles, pipelined conv:
//   y[node,o] = sum_k x[node,k] * Wt[k,o]
// 8 warps = 4 row-bands (16) x 2 col-halves (32). smem ~92KB -> 2 blocks/SM.
// ---------------------------------------------------------------------------
extern "C" __global__ void __launch_bounds__(TBLOCK, 2)
rgcn_transform_mma(const float* __restrict__ x, int n_nodes, int n_tiles)
{
    extern __shared__ __align__(16) char smem[];
    __half* wt_s = (__half*)smem;                        // 512*72 halves (73728B)
    __half* xb   = (__half*)(smem + KTOT * LDP * 2);     // 2*64*72 halves (18432B)
    int* tile_s  = (int*)(smem + KTOT * LDP * 2 + 2 * MTILE * LDP * 2);

    const int t = threadIdx.x;
    const int warp = t >> 5;
    const int wm = (warp & 3) * 16;   // row band
    const int wn = (warp >> 2) * 32;  // col half

    {
        const float4* src = (const float4*)g_wt;
        float4* dst = (float4*)wt_s;
        #pragma unroll
        for (int i2 = 0; i2 < 18; i2++) dst[t + i2 * TBLOCK] = src[t + i2 * TBLOCK];
    }
    // wt_s visible by the first in-loop __syncthreads() before any mma.

    int tile = blockIdx.x;
    while (tile < n_tiles) {
        const int node0 = tile * MTILE;

        // fetch NEXT tile index early; latency hidden behind whole tile
        if (t == 0) *tile_s = atomicAdd(&g_tilectr, 1);

        wmma::fragment<wmma::accumulator, 16, 16, 16, float> facc[2];
        wmma::fill_fragment(facc[0], 0.0f);
        wmma::fill_fragment(facc[1], 0.0f);

        // prefetch chunk 0 into registers (64 rows x 16 float4 = 4/thread)
        float4 pf[4];
        #pragma unroll
        for (int it = 0; it < 4; it++) {
            int f = t + it * TBLOCK;
            int row = f >> 4, c4 = f & 15;
            int node = node0 + row;
            pf[it] = (node < n_nodes)
                ? ((const float4*)x)[(size_t)node * (KTOT / 4) + c4]
                : make_float4(0.f, 0.f, 0.f, 0.f);
        }

        for (int c = 0; c < NCHUNKS; c++) {
            __half* xcur = xb + (c & 1) * (MTILE * LDP);

            // cvt + store prefetched chunk c
            #pragma unroll
            for (int it = 0; it < 4; it++) {
                int f = t + it * TBLOCK;
                int row = f >> 4, c4 = f & 15;
                __half2 h0 = __floats2half2_rn(pf[it].x, pf[it].y);
                __half2 h1 = __floats2half2_rn(pf[it].z, pf[it].w);
                uint2 st;
                st.x = *(uint32_t*)&h0;
                st.y = *(uint32_t*)&h1;
                *(uint2*)((char*)xcur + row * (LDP * 2) + c4 * 8) = st;
            }
            __syncthreads();   // conv(c) visible; mma(c-1) readers of other buf done

            // prefetch chunk c+1 (overlaps with mma below)
            if (c + 1 < NCHUNKS) {
                #pragma unroll
                for (int it = 0; it < 4; it++) {
                    int f = t + it * TBLOCK;
                    int row = f >> 4, c4 = f & 15;
                    int node = node0 + row;
                    pf[it] = (node < n_nodes)
                        ? ((const float4*)x)[(size_t)node * (KTOT / 4) + (c + 1) * 16 + c4]
                        : make_float4(0.f, 0.f, 0.f, 0.f);
                }
            }

            #pragma unroll
            for (int kk = 0; kk < 4; kk++) {
                wmma::fragment<wmma::matrix_a, 16, 16, 16, __half, wmma::row_major> fa;
                wmma::load_matrix_sync(fa, xcur + wm * LDP + kk * 16, LDP);
                const __half* wrow = wt_s + (c * KCH + kk * 16) * LDP + wn;
                #pragma unroll
                for (int ni = 0; ni < 2; ni++) {
                    wmma::fragment<wmma::matrix_b, 16, 16, 16, __half, wmma::row_major> fb;
                    wmma::load_matrix_sync(fb, wrow + ni * 16, LDP);
                    wmma::mma_sync(facc[ni], fa, fb, facc[ni]);
                }
            }
        }

        __syncthreads();     // all mma reads of xb done
        float* stage = (float*)xb;   // 64*64 floats = 16384B <= 18432B
        #pragma unroll
        for (int ni = 0; ni < 2; ni++)
            wmma::store_matrix_sync(stage + wm * D_OUT + wn + ni * 16,
                                    facc[ni], D_OUT, wmma::mem_row_major);
        __syncthreads();

        #pragma unroll
        for (int it = 0; it < 4; it++) {
            int f = t + it * TBLOCK;
            int row = f >> 4, q = f & 15;
            int node = node0 + row;
            if (node < n_nodes) {
                float4 v = *(const float4*)(stage + row * D_OUT + q * 4);
                __half2 h0 = __floats2half2_rn(v.x, v.y);
                __half2 h1 = __floats2half2_rn(v.z, v.w);
                uint2 st;
                st.x = *(uint32_t*)&h0;
                st.y = *(uint32_t*)&h1;
                *(uint2*)(g_y + (size_t)node * D_OUT + q * 4) = st;
            }
        }
        __syncthreads();     // stage reads done; tile_s stable
        tile = *tile_s;
    }
}

// ---------------------------------------------------------------------------
// CSR build: one memset(g_cnt incl. pub tail) -> hist -> fused scan -> fill
// ---------------------------------------------------------------------------
extern "C" __global__ void rgcn_hist(const int* __restrict__ edst, int n_edges)
{
    int e = blockIdx.x * blockDim.x + threadIdx.x;
    if (e < n_edges) atomicAdd(&g_cnt[edst[e]], 1);
}

// single-pass scan, grid <= 16 blocks, parallel publish/poll
extern "C" __global__ void __launch_bounds__(1024, 1)
rgcn_scan_fused(int n_nodes)
{
    __shared__ int wtot[32];
    __shared__ int preds[16];
    __shared__ int bp_sh;
    const int t = threadIdx.x, lane = t & 31, wid = t >> 5;
    const int b = blockIdx.x;
    volatile ull* pub = (volatile ull*)(g_cnt + ((n_nodes + 1) & ~1));

    int base = b * SCAN_PER + t * 4;
    int v[4];
    if (base + 3 < n_nodes) {
        int4 q = *(const int4*)(g_cnt + base);
        v[0] = q.x; v[1] = q.y; v[2] = q.z; v[3] = q.w;
    } else {
        #pragma unroll
        for (int j = 0; j < 4; j++) {
            int idx = base + j;
            v[j] = (idx < n_nodes) ? g_cnt[idx] : 0;
        }
    }
    int tsum = v[0] + v[1] + v[2] + v[3];
    int s = tsum;
    #pragma unroll
    for (int d = 1; d < 32; d <<= 1) {
        int u = __shfl_up_sync(0xffffffffu, s, d);
        if (lane >= d) s += u;
    }
    if (lane == 31) wtot[wid] = s;
    __syncthreads();
    if (wid == 0) {
        int wv = wtot[lane];
        #pragma unroll
        for (int d = 1; d < 32; d <<= 1) {
            int u = __shfl_up_sync(0xffffffffu, wv, d);
            if (lane >= d) wv += u;
        }
        wtot[lane] = wv;
    }
    __syncthreads();
    int local_excl = (s - tsum) + (wid ? wtot[wid - 1] : 0);
    int block_total = wtot[31];

    if (t == 0)
        pub[b] = (1ULL << 32) | (unsigned)block_total;
    if (t < b) {
        ull pv;
        do { pv = pub[t]; } while ((pv >> 32) == 0);
        preds[t] = (int)(unsigned)pv;
    }
    __syncthreads();
    if (t == 0) {
        int r = 0;
        for (int j = 0; j < b; j++) r += preds[j];
        bp_sh = r;
    }
    __syncthreads();

    int off = bp_sh + local_excl;
    #pragma unroll
    for (int j = 0; j < 4; j++) {
        int idx = base + j;
        if (idx < n_nodes) {
            g_start[idx] = off;
            g_cnt[idx]   = off;
            if (idx == n_nodes - 1) g_start[n_nodes] = off + v[j];
            off += v[j];
        }
    }
}

extern "C" __global__ void rgcn_fill(const int*   __restrict__ esrc,
                                     const int*   __restrict__ edst,
                                     const float* __restrict__ ew,
                                     int n_edges)
{
    int e = blockIdx.x * blockDim.x + threadIdx.x;
    if (e >= n_edges) return;
    int d = edst[e];
    int pos = atomicAdd(&g_cnt[d], 1);
    __half hw = __float2half_rn(ew[e]);
    g_elist[pos] = (uint32_t)esrc[e] | ((uint32_t)*(unsigned short*)&hw << 16);
}

// ---------------------------------------------------------------------------
// Aggregate: one warp per dst node; each lane owns 2 outputs. No atomics.
// ---------------------------------------------------------------------------
__device__ __forceinline__ float2 yfrag(uint32_t src, int lane)
{
    unsigned q = *((const unsigned*)g_y + ((size_t)src << 5) + lane);
    __half2 h; *(unsigned*)&h = q;
    return __half22float2(h);
}

extern "C" __global__ void __launch_bounds__(256, 8)
rgcn_aggregate(float* __restrict__ out, int n_nodes)
{
    int gid = blockIdx.x * blockDim.x + threadIdx.x;
    int n = gid >> 5;
    if (n >= n_nodes) return;
    int lane = gid & 31;
    int e  = g_start[n];
    int e1 = g_start[n + 1];
    float2 acc = make_float2(0.f, 0.f);

    for (; e + 8 <= e1; e += 8) {
        uint32_t p[8];
        #pragma unroll
        for (int j = 0; j < 8; j++) p[j] = g_elist[e + j];
        float2 f[8];
        #pragma unroll
        for (int j = 0; j < 8; j++) f[j] = yfrag(p[j] & 0xFFFFu, lane);
        #pragma unroll
        for (int j = 0; j < 8; j++) {
            unsigned short wb = (unsigned short)(p[j] >> 16);
            float w = __half2float(*(__half*)&wb);
            acc.x += w * f[j].x;
            acc.y += w * f[j].y;
        }
    }
    if (e + 4 <= e1) {
        uint32_t p[4];
        #pragma unroll
        for (int j = 0; j < 4; j++) p[j] = g_elist[e + j];
        float2 f[4];
        #pragma unroll
        for (int j = 0; j < 4; j++) f[j] = yfrag(p[j] & 0xFFFFu, lane);
        #pragma unroll
        for (int j = 0; j < 4; j++) {
            unsigned short wb = (unsigned short)(p[j] >> 16);
            float w = __half2float(*(__half*)&wb);
            acc.x += w * f[j].x;
            acc.y += w * f[j].y;
        }
        e += 4;
    }
    for (; e < e1; e++) {
        uint32_t p = g_elist[e];
        float2 f = yfrag(p & 0xFFFFu, lane);
        unsigned short wb = (unsigned short)(p >> 16);
        float w = __half2float(*(__half*)&wb);
        acc.x += w * f.x;
        acc.y += w * f.y;
    }
    *(float2*)(out + (size_t)n * D_OUT + lane * 2) = acc;
}

// ---------------------------------------------------------------------------
extern "C" void kernel_launch(void* const* d_in, const int* in_sizes, int n_in,
                              void* d_out, int out_size)
{
    const float* x    = (const float*)d_in[0];
    const int*   esrc = (const int*)  d_in[1];
    const int*   edst = (const int*)  d_in[2];
    const float* ew   = (const float*)d_in[3];
    const float* wb   = (const float*)d_in[4];
    const float* wrel = (const float*)d_in[5];
    float* out = (float*)d_out;

    const int n_nodes = in_sizes[0] / (D_FEAT * N_REL);
    const int n_edges = in_sizes[1];
    const int n_tiles = (n_nodes + MTILE - 1) / MTILE;
    const int scan_blocks = (n_nodes + SCAN_PER - 1) / SCAN_PER;
    const int tgrid = n_tiles < TGRID ? n_tiles : TGRID;

    const int mma_smem = KTOT * LDP * 2 + 2 * MTILE * LDP * 2 + 16;  // ~92KB
    cudaFuncSetAttribute(rgcn_transform_mma,
                         cudaFuncAttributeMaxDynamicSharedMemorySize, mma_smem);

    // fork stream + events (host-side; outside graph replay cost)
    cudaStream_t s1;
    cudaStreamCreateWithFlags(&s1, cudaStreamNonBlocking);
    cudaEvent_t evFork, evJoin;
    cudaEventCreateWithFlags(&evFork, cudaEventDisableTiming);
    cudaEventCreateWithFlags(&evJoin, cudaEventDisableTiming);

    // branch A (s1): weights + counter init + HMMA transform (dynamic tiles)
    cudaEventRecord(evFork, 0);
    cudaStreamWaitEvent(s1, evFork, 0);
    rgcn_wt_build<<<(KTOT * D_OUT + 255) / 256, 256, 0, s1>>>(wb, wrel, tgrid);
    rgcn_transform_mma<<<tgrid, TBLOCK, mma_smem, s1>>>(x, n_nodes, n_tiles);
    cudaEventRecord(evJoin, s1);

    // branch B (main): CSR build by dst. One memset covers counters + pub tail.
    void* cnt_ptr = nullptr;
    cudaGetSymbolAddress(&cnt_ptr, g_cnt);
    size_t zero_bytes = (size_t)(((n_nodes + 1) & ~1) + 32) * sizeof(int);
    cudaMemsetAsync(cnt_ptr, 0, zero_bytes, 0);

    rgcn_hist<<<(n_edges + 255) / 256, 256>>>(edst, n_edges);
    rgcn_scan_fused<<<scan_blocks, 1024>>>(n_nodes);
    rgcn_fill<<<(n_edges + 255) / 256, 256>>>(esrc, edst, ew, n_edges);

    // join, then gather-aggregate
    cudaStreamWaitEvent(0, evJoin, 0);
    int total_thr = n_nodes * 32;
    rgcn_aggregate<<<(total_thr + 255) / 256, 256>>>(out, n_nodes);
}